// round 3
// baseline (speedup 1.0000x reference)
#include <cuda_runtime.h>
#include <cstdint>

#define BHN   48
#define SEQ   1024
#define HD    64
#define TQ    64
#define TK    64
#define NQT   16          // SEQ / TQ
#define NTHREADS 128
#define LAM   0.01f
#define EPSV  1e-6f
#define CLV   20.0f
#define SCALE 0.125f

#define QT_STRIDE 68      // qT row stride (floats)
#define S_STRIDE  68      // S/W row stride (floats)
// smem: qT[64][68] | Sw[64][68] | KV[64][64]
#define SW_OFF  (64 * QT_STRIDE)
#define KV_OFF  (SW_OFF + 64 * S_STRIDE)
#define SMEM_FLOATS (KV_OFF + 64 * HD)

typedef unsigned long long u64;

__device__ __forceinline__ u64 pk2(float lo, float hi) {
    u64 r; asm("mov.b64 %0, {%1,%2};" : "=l"(r) : "f"(lo), "f"(hi)); return r;
}
__device__ __forceinline__ void fma2(u64& d, u64 a, u64 b) {
    asm("fma.rn.f32x2 %0, %1, %2, %0;" : "+l"(d) : "l"(a), "l"(b));
}
__device__ __forceinline__ u64 mul2(u64 a, u64 b) {
    u64 r; asm("mul.rn.f32x2 %0, %1, %2;" : "=l"(r) : "l"(a), "l"(b)); return r;
}
// 16B-chunk swizzle for the KV buffer: spreads banks for loader stores,
// kg-paired GEMM reads, and dg-paired V reads simultaneously.
__device__ __forceinline__ int swz(int row) { return (row ^ (row >> 3)) & 7; }

__global__ void __launch_bounds__(NTHREADS, 3)
rse_attn(const float* __restrict__ gq, const float* __restrict__ gk,
         const float* __restrict__ gv, const float* __restrict__ gcos,
         const float* __restrict__ gsin, float* __restrict__ gout)
{
    extern __shared__ float smem[];
    float* qT = smem;            // [d][q]   stride QT_STRIDE
    float* Sw = smem + SW_OFF;   // [k][q]   stride S_STRIDE (dots -> beta -> w)
    float* KV = smem + KV_OFF;   // [k][d]   stride 64, 16B-chunk swizzled

    const int tid = threadIdx.x;
    const int idx = blockIdx.x;
    const int qt  = (NQT - 1) - (idx / BHN);   // heavy q-tiles first
    const int bh  = idx % BHN;
    const int q0  = qt * TQ;
    const size_t base = (size_t)bh * SEQ * HD;

    const int lrow  = tid & 63;   // loader / beta / scan query-or-row id
    const int lhalf = tid >> 6;
    const float fq  = (float)(q0 + lrow);

    const int qg = tid & 15;      // 4-query group (phase1 + phase3 + epilogue)
    const int kg = tid >> 4;      // 8-key group   (phase1)
    const int dg = tid >> 4;      // 8-dim group   (phase3)

    // ---- one-time: load Q, RoPE, store transposed qT[d][q] ----
    {
        const float* src = gq + base + (size_t)(q0 + lrow) * HD + lhalf * 32;
        const float* cc  = gcos + (q0 + lrow) * 32 + lhalf * 16;
        const float* ss  = gsin + (q0 + lrow) * 32 + lhalf * 16;
        #pragma unroll
        for (int j = 0; j < 8; j++) {
            float4 x = *(const float4*)(src + 4 * j);
            float2 c = *(const float2*)(cc + 2 * j);
            float2 s = *(const float2*)(ss + 2 * j);
            int d = lhalf * 32 + 4 * j;
            qT[(d + 0) * QT_STRIDE + lrow] = x.x * c.x - x.y * s.x;
            qT[(d + 1) * QT_STRIDE + lrow] = x.y * c.x + x.x * s.x;
            qT[(d + 2) * QT_STRIDE + lrow] = x.z * c.y - x.w * s.y;
            qT[(d + 3) * QT_STRIDE + lrow] = x.w * c.y + x.z * s.y;
        }
    }

    u64 acc3[4][4];
    #pragma unroll
    for (int j = 0; j < 4; j++)
        #pragma unroll
        for (int i = 0; i < 4; i++) acc3[j][i] = 0ull;
    float rem = 1.f, ws = 0.f;

    for (int h = 0; h <= qt; h++) {
        const int k0 = h * TK;
        __syncthreads();   // prior phase3 done with KV/Sw; qT store visible

        // ---- load K chunk, RoPE, store swizzled into KV ----
        {
            const float* src = gk + base + (size_t)(k0 + lrow) * HD + lhalf * 32;
            const float* cc  = gcos + (k0 + lrow) * 32 + lhalf * 16;
            const float* ss  = gsin + (k0 + lrow) * 32 + lhalf * 16;
            const int sw = swz(lrow);
            #pragma unroll
            for (int j = 0; j < 8; j++) {
                float4 x = *(const float4*)(src + 4 * j);
                float2 c = *(const float2*)(cc + 2 * j);
                float2 s = *(const float2*)(ss + 2 * j);
                float4 kr;
                kr.x = x.x * c.x - x.y * s.x;
                kr.y = x.y * c.x + x.x * s.x;
                kr.z = x.z * c.y - x.w * s.y;
                kr.w = x.w * c.y + x.z * s.y;
                int col4 = (lhalf * 8 + j) ^ sw;
                *(float4*)(KV + lrow * HD + col4 * 4) = kr;
            }
        }
        __syncthreads();

        // ---- phase 1: S[8k x 4q] = K_rope · Q_rope^T (register GEMM) ----
        {
            u64 a[8][2];
            #pragma unroll
            for (int i = 0; i < 8; i++) { a[i][0] = 0ull; a[i][1] = 0ull; }
            int swk[8];
            #pragma unroll
            for (int i = 0; i < 8; i++) swk[i] = swz(kg * 8 + i);

            #pragma unroll 4
            for (int ds = 0; ds < 16; ds++) {
                u64 qq[4][2];
                #pragma unroll
                for (int j = 0; j < 4; j++) {
                    float4 qv = *(const float4*)(qT + (4 * ds + j) * QT_STRIDE + qg * 4);
                    qq[j][0] = pk2(qv.x, qv.y);
                    qq[j][1] = pk2(qv.z, qv.w);
                }
                #pragma unroll
                for (int i = 0; i < 8; i++) {
                    int krow = kg * 8 + i;
                    float4 kv = *(const float4*)(KV + krow * HD + ((ds ^ swk[i]) * 4));
                    u64 s0 = pk2(kv.x, kv.x);
                    fma2(a[i][0], s0, qq[0][0]); fma2(a[i][1], s0, qq[0][1]);
                    u64 s1 = pk2(kv.y, kv.y);
                    fma2(a[i][0], s1, qq[1][0]); fma2(a[i][1], s1, qq[1][1]);
                    u64 s2 = pk2(kv.z, kv.z);
                    fma2(a[i][0], s2, qq[2][0]); fma2(a[i][1], s2, qq[2][1]);
                    u64 s3 = pk2(kv.w, kv.w);
                    fma2(a[i][0], s3, qq[3][0]); fma2(a[i][1], s3, qq[3][1]);
                }
            }
            #pragma unroll
            for (int i = 0; i < 8; i++) {
                ulonglong2 t; t.x = a[i][0]; t.y = a[i][1];
                *(ulonglong2*)(Sw + (kg * 8 + i) * S_STRIDE + qg * 4) = t;
            }
        }
        __syncthreads();

        // ---- load V (overwrites K in KV) + beta precompute (all threads) ----
        {
            const float* src = gv + base + (size_t)(k0 + lrow) * HD + lhalf * 32;
            const int sw = swz(lrow);
            #pragma unroll
            for (int j = 0; j < 8; j++) {
                float4 x = *(const float4*)(src + 4 * j);
                int col4 = (lhalf * 8 + j) ^ sw;
                *(float4*)(KV + lrow * HD + col4 * 4) = x;
            }
        }
        {
            const int kbase = lhalf * 32;
            #pragma unroll 4
            for (int k = 0; k < 32; k++) {
                int kk = kbase + k;
                float dot = Sw[kk * S_STRIDE + lrow];
                float lg = fmaf(dot, SCALE, LAM * ((float)(k0 + kk) - fq));
                lg = fminf(fmaxf(lg, -CLV), CLV);
                float beta = __fdividef(1.f, 1.f + __expf(-lg));
                Sw[kk * S_STRIDE + lrow] = beta;
            }
        }
        __syncthreads();

        // ---- scan (threads 0..63): sequential rem-chain over 64 betas ----
        if (tid < 64) {
            const int nvalid = (h < qt) ? 64 : (lrow + 1);
            #pragma unroll 1
            for (int g = 0; g < 8; g++) {
                float b[8];
                #pragma unroll
                for (int j = 0; j < 8; j++)
                    b[j] = Sw[(g * 8 + j) * S_STRIDE + lrow];
                #pragma unroll
                for (int j = 0; j < 8; j++) {
                    float w = (g * 8 + j < nvalid) ? b[j] * rem : 0.f;
                    rem = fmaxf(fmaf(-w, rem, rem), EPSV);
                    ws += w;
                    b[j] = w;
                }
                #pragma unroll
                for (int j = 0; j < 8; j++)
                    Sw[(g * 8 + j) * S_STRIDE + lrow] = b[j];
            }
        }
        __syncthreads();

        // ---- phase 3: O[4q x 8d] += W^T · V (register GEMM) ----
        #pragma unroll 4
        for (int k = 0; k < TK; k++) {
            float4 w = *(const float4*)(Sw + k * S_STRIDE + qg * 4);
            int sk = swz(k);
            ulonglong2 va = *(const ulonglong2*)(KV + k * HD + (((dg * 2)     ^ sk) * 4));
            ulonglong2 vb = *(const ulonglong2*)(KV + k * HD + (((dg * 2 + 1) ^ sk) * 4));
            u64 s;
            s = pk2(w.x, w.x);
            fma2(acc3[0][0], s, va.x); fma2(acc3[0][1], s, va.y);
            fma2(acc3[0][2], s, vb.x); fma2(acc3[0][3], s, vb.y);
            s = pk2(w.y, w.y);
            fma2(acc3[1][0], s, va.x); fma2(acc3[1][1], s, va.y);
            fma2(acc3[1][2], s, vb.x); fma2(acc3[1][3], s, vb.y);
            s = pk2(w.z, w.z);
            fma2(acc3[2][0], s, va.x); fma2(acc3[2][1], s, va.y);
            fma2(acc3[2][2], s, vb.x); fma2(acc3[2][3], s, vb.y);
            s = pk2(w.w, w.w);
            fma2(acc3[3][0], s, va.x); fma2(acc3[3][1], s, va.y);
            fma2(acc3[3][2], s, vb.x); fma2(acc3[3][3], s, vb.y);
        }
    }

    // ---- epilogue: share wsum via qT row 0, normalize, write out ----
    __syncthreads();
    if (tid < 64) qT[lrow] = ws;
    __syncthreads();
    float4 wsv = *(const float4*)(qT + qg * 4);
    float inv[4];
    inv[0] = __fdividef(1.f, fmaxf(wsv.x, EPSV));
    inv[1] = __fdividef(1.f, fmaxf(wsv.y, EPSV));
    inv[2] = __fdividef(1.f, fmaxf(wsv.z, EPSV));
    inv[3] = __fdividef(1.f, fmaxf(wsv.w, EPSV));
    #pragma unroll
    for (int j = 0; j < 4; j++) {
        u64 iv = pk2(inv[j], inv[j]);
        float* dst = gout + base + (size_t)(q0 + qg * 4 + j) * HD + dg * 8;
        ulonglong2 o;
        o.x = mul2(acc3[j][0], iv);
        o.y = mul2(acc3[j][1], iv);
        *(ulonglong2*)(dst) = o;
        o.x = mul2(acc3[j][2], iv);
        o.y = mul2(acc3[j][3], iv);
        *(ulonglong2*)(dst + 4) = o;
    }
}

extern "C" void kernel_launch(void* const* d_in, const int* in_sizes, int n_in,
                              void* d_out, int out_size)
{
    (void)in_sizes; (void)n_in; (void)out_size;
    const float* q    = (const float*)d_in[0];
    const float* k    = (const float*)d_in[1];
    const float* v    = (const float*)d_in[2];
    const float* cosc = (const float*)d_in[3];
    const float* sinc = (const float*)d_in[4];
    float* out = (float*)d_out;

    const int smem_bytes = SMEM_FLOATS * (int)sizeof(float);  // ~51.2 KB
    cudaFuncSetAttribute(rse_attn, cudaFuncAttributeMaxDynamicSharedMemorySize,
                         smem_bytes);
    rse_attn<<<NQT * BHN, NTHREADS, smem_bytes>>>(q, k, v, cosc, sinc, out);
}

// round 4
// speedup vs baseline: 1.1261x; 1.1261x over previous
#include <cuda_runtime.h>
#include <cstdint>

#define BHN   48
#define SEQ   1024
#define HD    64
#define TK    64
#define NQT   16          // SEQ / 64
#define NTHREADS 128
#define LAM   0.01f
#define EPSV  1e-6f
#define CLV   20.0f
#define SCALE 0.125f

#define QT_STRIDE 68
#define S_STRIDE  68
#define KV_STRIDE 68
// smem: qT[64][68] | Sw[64][68] | KV[64][68]
#define SW_OFF  (64 * QT_STRIDE)
#define KV_OFF  (SW_OFF + 64 * S_STRIDE)
#define SMEM_FLOATS (KV_OFF + 64 * KV_STRIDE)

typedef unsigned long long u64;

__device__ __forceinline__ u64 pk2(float lo, float hi) {
    u64 r; asm("mov.b64 %0, {%1,%2};" : "=l"(r) : "f"(lo), "f"(hi)); return r;
}
__device__ __forceinline__ void unpk2(u64 v, float& lo, float& hi) {
    asm("mov.b64 {%0,%1}, %2;" : "=f"(lo), "=f"(hi) : "l"(v));
}
__device__ __forceinline__ void fma2(u64& d, u64 a, u64 b) {
    asm("fma.rn.f32x2 %0, %1, %2, %0;" : "+l"(d) : "l"(a), "l"(b));
}
__device__ __forceinline__ u64 mul2(u64 a, u64 b) {
    u64 r; asm("mul.rn.f32x2 %0, %1, %2;" : "=l"(r) : "l"(a), "l"(b)); return r;
}
__device__ __forceinline__ float sigm(float lg) {
    return __fdividef(1.f, 1.f + __expf(-lg));
}

__global__ void __launch_bounds__(NTHREADS, 3)
rse_attn(const float* __restrict__ gq, const float* __restrict__ gk,
         const float* __restrict__ gv, const float* __restrict__ gcos,
         const float* __restrict__ gsin, float* __restrict__ gout)
{
    extern __shared__ float smem[];
    float* qT = smem;            // [d][q]  RoPE'd Q transposed
    float* Sw = smem + SW_OFF;   // [k][q]  beta then w
    float* KV = smem + KV_OFF;   // [k][d]  K (phase1) then V (phase3)

    const int tid = threadIdx.x;
    const int idx = blockIdx.x;
    const int qt  = (NQT - 1) - (idx / BHN);   // heavy q-tiles first
    const int bh  = idx % BHN;
    const int q0  = qt * TK;
    const size_t base = (size_t)bh * SEQ * HD;

    const int lrow  = tid & 63;
    const int lhalf = tid >> 6;
    const int qg = tid & 15;      // 4-query group
    const int kg = tid >> 4;      // 8-key group / 8-dim group
    const int dg = kg;

    // ---- one-time: load Q, RoPE, store transposed qT[d][q] ----
    {
        const float* src = gq + base + (size_t)(q0 + lrow) * HD + lhalf * 32;
        const float* cc  = gcos + (q0 + lrow) * 32 + lhalf * 16;
        const float* ss  = gsin + (q0 + lrow) * 32 + lhalf * 16;
        #pragma unroll
        for (int j = 0; j < 8; j++) {
            float4 x = *(const float4*)(src + 4 * j);
            float2 c = *(const float2*)(cc + 2 * j);
            float2 s = *(const float2*)(ss + 2 * j);
            int d = lhalf * 32 + 4 * j;
            qT[(d + 0) * QT_STRIDE + lrow] = x.x * c.x - x.y * s.x;
            qT[(d + 1) * QT_STRIDE + lrow] = x.y * c.x + x.x * s.x;
            qT[(d + 2) * QT_STRIDE + lrow] = x.z * c.y - x.w * s.y;
            qT[(d + 3) * QT_STRIDE + lrow] = x.w * c.y + x.z * s.y;
        }
    }

    u64 acc3[4][4];
    #pragma unroll
    for (int j = 0; j < 4; j++)
        #pragma unroll
        for (int i = 0; i < 4; i++) acc3[j][i] = 0ull;
    float rem = 1.f, ws = 0.f;

    for (int h = 0; h <= qt; h++) {
        const int k0 = h * TK;
        __syncthreads();   // prior phase3 done reading KV/Sw; qT visible

        // ---- load K chunk, RoPE, into KV (row-contiguous, padded) ----
        {
            const float* src = gk + base + (size_t)(k0 + lrow) * HD + lhalf * 32;
            const float* cc  = gcos + (k0 + lrow) * 32 + lhalf * 16;
            const float* ss  = gsin + (k0 + lrow) * 32 + lhalf * 16;
            float* dst = KV + lrow * KV_STRIDE + lhalf * 32;
            #pragma unroll
            for (int j = 0; j < 8; j++) {
                float4 x = *(const float4*)(src + 4 * j);
                float2 c = *(const float2*)(cc + 2 * j);
                float2 s = *(const float2*)(ss + 2 * j);
                float4 kr;
                kr.x = x.x * c.x - x.y * s.x;
                kr.y = x.y * c.x + x.x * s.x;
                kr.z = x.z * c.y - x.w * s.y;
                kr.w = x.w * c.y + x.z * s.y;
                *(float4*)(dst + 4 * j) = kr;
            }
        }
        __syncthreads();

        // ---- phase 1: S[8k x 4q] = K·Qᵀ (register GEMM), fused beta ----
        {
            u64 a[8][2];
            #pragma unroll
            for (int i = 0; i < 8; i++) { a[i][0] = 0ull; a[i][1] = 0ull; }
            const float* kb = KV + (kg * 8) * KV_STRIDE;
            const float* qb = qT + qg * 4;

            #pragma unroll 4
            for (int ds = 0; ds < 16; ds++) {
                u64 qq[4][2];
                #pragma unroll
                for (int j = 0; j < 4; j++) {
                    float4 qv = *(const float4*)(qb + (4 * ds + j) * QT_STRIDE);
                    qq[j][0] = pk2(qv.x, qv.y);
                    qq[j][1] = pk2(qv.z, qv.w);
                }
                #pragma unroll
                for (int i = 0; i < 8; i++) {
                    float4 kv = *(const float4*)(kb + i * KV_STRIDE + ds * 4);
                    u64 s0 = pk2(kv.x, kv.x);
                    fma2(a[i][0], s0, qq[0][0]); fma2(a[i][1], s0, qq[0][1]);
                    u64 s1 = pk2(kv.y, kv.y);
                    fma2(a[i][0], s1, qq[1][0]); fma2(a[i][1], s1, qq[1][1]);
                    u64 s2 = pk2(kv.z, kv.z);
                    fma2(a[i][0], s2, qq[2][0]); fma2(a[i][1], s2, qq[2][1]);
                    u64 s3 = pk2(kv.w, kv.w);
                    fma2(a[i][0], s3, qq[3][0]); fma2(a[i][1], s3, qq[3][1]);
                }
            }
            // fused: dot -> logit -> clamp -> beta, stored to Sw
            const float fkq = (float)(k0 + kg * 8 - q0 - qg * 4);  // (k - q) at i=0,j=0
            #pragma unroll
            for (int i = 0; i < 8; i++) {
                float d0, d1, d2, d3;
                unpk2(a[i][0], d0, d1);
                unpk2(a[i][1], d2, d3);
                const float pd = (fkq + (float)i) * LAM;
                float4 bo;
                bo.x = sigm(fminf(fmaxf(fmaf(d0, SCALE, pd            ), -CLV), CLV));
                bo.y = sigm(fminf(fmaxf(fmaf(d1, SCALE, pd - LAM      ), -CLV), CLV));
                bo.z = sigm(fminf(fmaxf(fmaf(d2, SCALE, pd - 2.f * LAM), -CLV), CLV));
                bo.w = sigm(fminf(fmaxf(fmaf(d3, SCALE, pd - 3.f * LAM), -CLV), CLV));
                *(float4*)(Sw + (kg * 8 + i) * S_STRIDE + qg * 4) = bo;
            }
        }
        __syncthreads();

        // ---- load V (overwrites K) while threads<64 run the scan ----
        {
            const float* src = gv + base + (size_t)(k0 + lrow) * HD + lhalf * 32;
            float* dst = KV + lrow * KV_STRIDE + lhalf * 32;
            #pragma unroll
            for (int j = 0; j < 8; j++)
                *(float4*)(dst + 4 * j) = *(const float4*)(src + 4 * j);
        }
        if (tid < 64) {
            const int nvalid = (h < qt) ? 64 : (lrow + 1);
            #pragma unroll 1
            for (int g = 0; g < 8; g++) {
                float b[8];
                #pragma unroll
                for (int j = 0; j < 8; j++)
                    b[j] = Sw[(g * 8 + j) * S_STRIDE + lrow];
                #pragma unroll
                for (int j = 0; j < 8; j++) {
                    float w = (g * 8 + j < nvalid) ? b[j] * rem : 0.f;
                    rem = fmaxf(fmaf(-w, rem, rem), EPSV);
                    ws += w;
                    b[j] = w;
                }
                #pragma unroll
                for (int j = 0; j < 8; j++)
                    Sw[(g * 8 + j) * S_STRIDE + lrow] = b[j];
            }
        }
        __syncthreads();

        // ---- phase 3: O[4q x 8d] += Wᵀ·V (register GEMM) ----
        {
            const float* wb = Sw + qg * 4;
            const float* vb = KV + dg * 8;
            #pragma unroll 4
            for (int k = 0; k < TK; k++) {
                float4 w = *(const float4*)(wb + k * S_STRIDE);
                ulonglong2 va = *(const ulonglong2*)(vb + k * KV_STRIDE);
                ulonglong2 vc = *(const ulonglong2*)(vb + k * KV_STRIDE + 4);
                u64 s;
                s = pk2(w.x, w.x);
                fma2(acc3[0][0], s, va.x); fma2(acc3[0][1], s, va.y);
                fma2(acc3[0][2], s, vc.x); fma2(acc3[0][3], s, vc.y);
                s = pk2(w.y, w.y);
                fma2(acc3[1][0], s, va.x); fma2(acc3[1][1], s, va.y);
                fma2(acc3[1][2], s, vc.x); fma2(acc3[1][3], s, vc.y);
                s = pk2(w.z, w.z);
                fma2(acc3[2][0], s, va.x); fma2(acc3[2][1], s, va.y);
                fma2(acc3[2][2], s, vc.x); fma2(acc3[2][3], s, vc.y);
                s = pk2(w.w, w.w);
                fma2(acc3[3][0], s, va.x); fma2(acc3[3][1], s, va.y);
                fma2(acc3[3][2], s, vc.x); fma2(acc3[3][3], s, vc.y);
            }
        }
    }

    // ---- epilogue: share wsum via qT row 0, normalize, write out ----
    __syncthreads();
    if (tid < 64) qT[lrow] = ws;
    __syncthreads();
    float4 wsv = *(const float4*)(qT + qg * 4);
    float inv[4];
    inv[0] = __fdividef(1.f, fmaxf(wsv.x, EPSV));
    inv[1] = __fdividef(1.f, fmaxf(wsv.y, EPSV));
    inv[2] = __fdividef(1.f, fmaxf(wsv.z, EPSV));
    inv[3] = __fdividef(1.f, fmaxf(wsv.w, EPSV));
    #pragma unroll
    for (int j = 0; j < 4; j++) {
        u64 iv = pk2(inv[j], inv[j]);
        float* dst = gout + base + (size_t)(q0 + qg * 4 + j) * HD + dg * 8;
        ulonglong2 o;
        o.x = mul2(acc3[j][0], iv);
        o.y = mul2(acc3[j][1], iv);
        *(ulonglong2*)(dst) = o;
        o.x = mul2(acc3[j][2], iv);
        o.y = mul2(acc3[j][3], iv);
        *(ulonglong2*)(dst + 4) = o;
    }
}

extern "C" void kernel_launch(void* const* d_in, const int* in_sizes, int n_in,
                              void* d_out, int out_size)
{
    (void)in_sizes; (void)n_in; (void)out_size;
    const float* q    = (const float*)d_in[0];
    const float* k    = (const float*)d_in[1];
    const float* v    = (const float*)d_in[2];
    const float* cosc = (const float*)d_in[3];
    const float* sinc = (const float*)d_in[4];
    float* out = (float*)d_out;

    const int smem_bytes = SMEM_FLOATS * (int)sizeof(float);  // ~52.2 KB
    cudaFuncSetAttribute(rse_attn, cudaFuncAttributeMaxDynamicSharedMemorySize,
                         smem_bytes);
    rse_attn<<<NQT * BHN, NTHREADS, smem_bytes>>>(q, k, v, cosc, sinc, out);
}